// round 10
// baseline (speedup 1.0000x reference)
#include <cuda_runtime.h>
#include <cuda_fp16.h>
#include <math.h>

#define NN 8192
#define DD 256
#define KK 16
#define KSEL 17
#define RS28 28           // refine candidates per row
#define MS 24             // local streaming top-M per row
#define BM 64
#define BN 64
#define NTILE 128         // 8192/64
#define JTS 8             // thresh-pass sample tiles (512 cols)
#define MST 20            // thresh-pass top-M -> tau
#define RSB 264           // smem row stride in fp16 elements (528B)
#define CAP 1024
#define ULLINF 0xFFFFFFFFFFFFFFFFull

__device__ float g_sq[NN];
__device__ float g_tau[NN];
__device__ __half2 g_fh16[NN * DD / 2];
__device__ int g_bcnt[NN];
__device__ unsigned long long g_buf[(size_t)NN * CAP];
__device__ unsigned long long g_loc[(size_t)NN * MS];
__device__ unsigned long long g_cand[NN * RS28];
__device__ unsigned long long g_best[NN * KSEL];

__device__ __forceinline__ unsigned smem_u32(const void* p) {
    unsigned a;
    asm("{ .reg .u64 t; cvta.to.shared.u64 t, %1; cvt.u32.u64 %0, t; }" : "=r"(a) : "l"(p));
    return a;
}
__device__ __forceinline__ unsigned mono(float f) {
    unsigned u = __float_as_uint(f);
    return (u & 0x80000000u) ? ~u : (u | 0x80000000u);
}
__device__ __forceinline__ float unmono(unsigned u) {
    return __uint_as_float((u & 0x80000000u) ? (u ^ 0x80000000u) : ~u);
}

#define CP16(dst, src) asm volatile("cp.async.cg.shared.global [%0], [%1], 16;" :: "r"(dst), "l"(src) : "memory")
#define CP_COMMIT()    asm volatile("cp.async.commit_group;" ::: "memory")
#define CP_WAIT(n)     asm volatile("cp.async.wait_group %0;" :: "n"(n) : "memory")
#define LDSM_X4(r0, r1, r2, r3, a) \
    asm volatile("ldmatrix.sync.aligned.m8n8.x4.shared.b16 {%0,%1,%2,%3}, [%4];" \
        : "=r"(r0), "=r"(r1), "=r"(r2), "=r"(r3) : "r"(a))
#define MMA_F16(d0, d1, a0, a1, a2, a3, b0, b1) \
    asm volatile("mma.sync.aligned.m16n8k16.row.col.f16.f16.f16.f16 " \
        "{%0,%1},{%2,%3,%4,%5},{%6,%7},{%0,%1};" \
        : "+r"(d0), "+r"(d1) \
        : "r"(a0), "r"(a1), "r"(a2), "r"(a3), "r"(b0), "r"(b1))

// ---------------- Kernel A: norms + fp16 convert + counter reset ----------------
__global__ void sq_kernel(const float* __restrict__ feats) {
    int gw = (blockIdx.x * blockDim.x + threadIdx.x) >> 5;
    int lane = threadIdx.x & 31;
    if (gw >= NN) return;
    const float4* rowp = (const float4*)(feats + (size_t)gw * DD);
    float4 a = rowp[lane];
    float4 b = rowp[lane + 32];
    float s = a.x*a.x + a.y*a.y + a.z*a.z + a.w*a.w
            + b.x*b.x + b.y*b.y + b.z*b.z + b.w*b.w;
    #pragma unroll
    for (int o = 16; o; o >>= 1) s += __shfl_xor_sync(0xffffffffu, s, o);
    if (lane == 0) { g_sq[gw] = s; g_bcnt[gw] = 0; }
    __half2* dst = g_fh16 + (size_t)gw * (DD / 2);
    dst[lane * 2]          = __floats2half2_rn(a.x, a.y);
    dst[lane * 2 + 1]      = __floats2half2_rn(a.z, a.w);
    dst[64 + lane * 2]     = __floats2half2_rn(b.x, b.y);
    dst[64 + lane * 2 + 1] = __floats2half2_rn(b.z, b.w);
}

// ---------------- Kernel T: sample 512 cols -> per-row tau (20th-smallest key) ----------------
struct SmemT {
    __half A[BM][RSB];
    __half B[2][BN][RSB];
    float sqB[2][BN];
    float thr[BM];
    int   cnt[BM];
    unsigned long long best[BM][MST];
    unsigned long long cand[BM][BN];
};

__device__ __forceinline__ void prefetch_BT(SmemT& sm, int s, int j0, int tid) {
    #pragma unroll
    for (int t = 0; t < 8; ++t) {
        int idx = t * 256 + tid;
        int r = idx >> 5, ch = idx & 31;
        unsigned dst = smem_u32(&sm.B[s][r][ch * 8]);
        const void* src = (const char*)g_fh16 + (((size_t)(j0 + r) * DD) + ch * 8) * 2;
        CP16(dst, src);
    }
    if (tid < 16) {
        unsigned dst = smem_u32(&sm.sqB[s][tid * 4]);
        const void* src = g_sq + j0 + tid * 4;
        CP16(dst, src);
    }
}

__global__ void __launch_bounds__(256, 1) thresh_kernel() {
    extern __shared__ char raw[];
    SmemT& sm = *reinterpret_cast<SmemT*>(raw);
    const int tid = threadIdx.x;
    const int lane = tid & 31;
    const int w = tid >> 5;
    const int wr = w >> 1;
    const int wc = w & 1;
    const int i0 = blockIdx.x * BM;

    #pragma unroll
    for (int t = 0; t < 8; ++t) {
        int idx = t * 256 + tid;
        int r = idx >> 5, ch = idx & 31;
        unsigned dst = smem_u32(&sm.A[r][ch * 8]);
        const void* src = (const char*)g_fh16 + (((size_t)(i0 + r) * DD) + ch * 8) * 2;
        CP16(dst, src);
    }
    CP_COMMIT();
    prefetch_BT(sm, 0, 0, tid);
    CP_COMMIT();

    if (tid < BM) {
        sm.thr[tid] = __int_as_float(0x7f800000);
        sm.cnt[tid] = 0;
        #pragma unroll
        for (int t = 0; t < MST; ++t) sm.best[tid][t] = 0xFF800000FFFFFFFFull;
    }

    const unsigned aAddr = smem_u32(&sm.A[wr * 16 + (lane & 15)][0]) + ((lane >> 4) << 4);
    const int rowB = wc * 32 + ((lane >> 4) << 3) + (lane & 7);
    const unsigned bColOff = ((lane >> 3) & 1) << 4;
    unsigned bAddrBase[2];
    bAddrBase[0] = smem_u32(&sm.B[0][rowB][0]) + bColOff;
    bAddrBase[1] = smem_u32(&sm.B[1][rowB][0]) + bColOff;

    const int R0 = wr * 16 + (lane >> 2);
    const int R1 = R0 + 8;
    const int cBase = wc * 32 + 2 * (lane & 3);

    for (int jt = 0; jt < JTS; ++jt) {
        const int s = jt & 1;
        const int j0 = jt * BN;

        if (jt + 1 < JTS) {
            prefetch_BT(sm, s ^ 1, (jt + 1) * BN, tid);
            CP_COMMIT();
            CP_WAIT(1);
        } else {
            CP_WAIT(0);
        }
        __syncthreads();

        unsigned acc[4][2];
        #pragma unroll
        for (int nt = 0; nt < 4; ++nt) { acc[nt][0] = 0u; acc[nt][1] = 0u; }

        const unsigned bA = bAddrBase[s];
        #pragma unroll
        for (int ks = 0; ks < 16; ++ks) {
            unsigned a0, a1, a2, a3;
            LDSM_X4(a0, a1, a2, a3, aAddr + ks * 32);
            unsigned p00, p01, p10, p11, q00, q01, q10, q11;
            LDSM_X4(p00, p01, p10, p11, bA + ks * 32);
            LDSM_X4(q00, q01, q10, q11, bA + 16 * (RSB * 2) + ks * 32);
            MMA_F16(acc[0][0], acc[0][1], a0, a1, a2, a3, p00, p01);
            MMA_F16(acc[1][0], acc[1][1], a0, a1, a2, a3, p10, p11);
            MMA_F16(acc[2][0], acc[2][1], a0, a1, a2, a3, q00, q01);
            MMA_F16(acc[3][0], acc[3][1], a0, a1, a2, a3, q10, q11);
        }

        const float t0 = sm.thr[R0];
        const float t1 = sm.thr[R1];
        const float* sq = sm.sqB[s];
        #pragma unroll
        for (int nt = 0; nt < 4; ++nt) {
            const int c = cBase + nt * 8;
            float2 f0 = __half22float2(*(__half2*)&acc[nt][0]);
            float2 f1 = __half22float2(*(__half2*)&acc[nt][1]);
            float v00 = fmaf(-2.f, f0.x, sq[c]);
            float v01 = fmaf(-2.f, f0.y, sq[c + 1]);
            float v10 = fmaf(-2.f, f1.x, sq[c]);
            float v11 = fmaf(-2.f, f1.y, sq[c + 1]);
            if (v00 < t0) { int p = atomicAdd(&sm.cnt[R0], 1);
                sm.cand[R0][p] = ((unsigned long long)mono(v00) << 32) | (unsigned)(j0 + c); }
            if (v01 < t0) { int p = atomicAdd(&sm.cnt[R0], 1);
                sm.cand[R0][p] = ((unsigned long long)mono(v01) << 32) | (unsigned)(j0 + c + 1); }
            if (v10 < t1) { int p = atomicAdd(&sm.cnt[R1], 1);
                sm.cand[R1][p] = ((unsigned long long)mono(v10) << 32) | (unsigned)(j0 + c); }
            if (v11 < t1) { int p = atomicAdd(&sm.cnt[R1], 1);
                sm.cand[R1][p] = ((unsigned long long)mono(v11) << 32) | (unsigned)(j0 + c + 1); }
        }
        __syncthreads();

        if (tid < BM) {
            int n = sm.cnt[tid];
            if (n) {
                sm.cnt[tid] = 0;
                unsigned long long* bl = sm.best[tid];
                for (int q = 0; q < n; ++q) {
                    unsigned long long key = sm.cand[tid][q];
                    if (key < bl[MST - 1]) {
                        int p = MST - 1;
                        while (p > 0 && bl[p - 1] > key) { bl[p] = bl[p - 1]; --p; }
                        bl[p] = key;
                    }
                }
                sm.thr[tid] = unmono((unsigned)(bl[MST - 1] >> 32));
            }
        }
    }

    if (tid < BM)
        g_tau[i0 + tid] = unmono((unsigned)(sm.best[tid][MST - 1] >> 32));
}

// ---------------- Kernel S: balanced cyclic symmetric screen ----------------
struct SmemS {
    __half A[BM][RSB];                 // 33792 B
    __half B[2][BN][RSB];              // 67584 B
    float sqB[2][BN], tauB[2][BN];
    float sqA[BM];
    float thr[BM];
    int   cnt[BM];
    unsigned long long best[BM][MS];   // 12288 B
    unsigned long long cand[BM][BN];   // 32768 B
};

__device__ __forceinline__ void prefetch_BS(SmemS& sm, int s, int j0, int tid) {
    #pragma unroll
    for (int t = 0; t < 8; ++t) {
        int idx = t * 256 + tid;
        int r = idx >> 5, ch = idx & 31;
        unsigned dst = smem_u32(&sm.B[s][r][ch * 8]);
        const void* src = (const char*)g_fh16 + (((size_t)(j0 + r) * DD) + ch * 8) * 2;
        CP16(dst, src);
    }
    if (tid < 16) {
        unsigned dst = smem_u32(&sm.sqB[s][tid * 4]);
        CP16(dst, (const void*)(g_sq + j0 + tid * 4));
    } else if (tid < 32) {
        int t = tid - 16;
        unsigned dst = smem_u32(&sm.tauB[s][t * 4]);
        CP16(dst, (const void*)(g_tau + j0 + t * 4));
    }
}

__device__ __forceinline__ void try_append(int row, float v, int col) {
    int p = atomicAdd(&g_bcnt[row], 1);
    if (p < CAP)
        g_buf[(size_t)row * CAP + p] = ((unsigned long long)mono(v) << 32) | (unsigned)col;
}

__global__ void __launch_bounds__(256, 1) screen_kernel() {
    extern __shared__ char raw[];
    SmemS& sm = *reinterpret_cast<SmemS*>(raw);
    const int tid = threadIdx.x;
    const int lane = tid & 31;
    const int w = tid >> 5;
    const int wr = w >> 1;
    const int wc = w & 1;
    const int it = blockIdx.x;
    const int i0 = it * BM;
    const int NT = (it < 64) ? 65 : 64;

    #pragma unroll
    for (int t = 0; t < 8; ++t) {
        int idx = t * 256 + tid;
        int r = idx >> 5, ch = idx & 31;
        unsigned dst = smem_u32(&sm.A[r][ch * 8]);
        const void* src = (const char*)g_fh16 + (((size_t)(i0 + r) * DD) + ch * 8) * 2;
        CP16(dst, src);
    }
    CP_COMMIT();
    prefetch_BS(sm, 0, i0, tid);   // t=0 tile is the diagonal: jt = it
    CP_COMMIT();

    if (tid < BM) {
        sm.sqA[tid] = g_sq[i0 + tid];
        sm.thr[tid] = __int_as_float(0x7f800000);
        sm.cnt[tid] = 0;
        #pragma unroll
        for (int t = 0; t < MS; ++t) sm.best[tid][t] = 0xFF800000FFFFFFFFull;
    }

    const unsigned aAddr = smem_u32(&sm.A[wr * 16 + (lane & 15)][0]) + ((lane >> 4) << 4);
    const int rowB = wc * 32 + ((lane >> 4) << 3) + (lane & 7);
    const unsigned bColOff = ((lane >> 3) & 1) << 4;
    unsigned bAddrBase[2];
    bAddrBase[0] = smem_u32(&sm.B[0][rowB][0]) + bColOff;
    bAddrBase[1] = smem_u32(&sm.B[1][rowB][0]) + bColOff;

    const int R0 = wr * 16 + (lane >> 2);
    const int R1 = R0 + 8;
    const int cBase = wc * 32 + 2 * (lane & 3);

    for (int t = 0; t < NT; ++t) {
        const int s = t & 1;
        const int jt = (it + t) & (NTILE - 1);
        const int j0 = jt * BN;
        const bool offdiag = (t != 0);

        if (t + 1 < NT) {
            prefetch_BS(sm, s ^ 1, ((it + t + 1) & (NTILE - 1)) * BN, tid);
            CP_COMMIT();
            CP_WAIT(1);
        } else {
            CP_WAIT(0);
        }
        __syncthreads();

        unsigned acc[4][2];
        #pragma unroll
        for (int nt = 0; nt < 4; ++nt) { acc[nt][0] = 0u; acc[nt][1] = 0u; }

        const unsigned bA = bAddrBase[s];
        #pragma unroll
        for (int ks = 0; ks < 16; ++ks) {
            unsigned a0, a1, a2, a3;
            LDSM_X4(a0, a1, a2, a3, aAddr + ks * 32);
            unsigned p00, p01, p10, p11, q00, q01, q10, q11;
            LDSM_X4(p00, p01, p10, p11, bA + ks * 32);
            LDSM_X4(q00, q01, q10, q11, bA + 16 * (RSB * 2) + ks * 32);
            MMA_F16(acc[0][0], acc[0][1], a0, a1, a2, a3, p00, p01);
            MMA_F16(acc[1][0], acc[1][1], a0, a1, a2, a3, p10, p11);
            MMA_F16(acc[2][0], acc[2][1], a0, a1, a2, a3, q00, q01);
            MMA_F16(acc[3][0], acc[3][1], a0, a1, a2, a3, q10, q11);
        }

        const float t0 = sm.thr[R0];
        const float t1 = sm.thr[R1];
        const float sqa0 = sm.sqA[R0];
        const float sqa1 = sm.sqA[R1];
        const float* sq = sm.sqB[s];
        const float* tb = sm.tauB[s];
        #pragma unroll
        for (int nt = 0; nt < 4; ++nt) {
            const int c = cBase + nt * 8;
            float2 f0 = __half22float2(*(__half2*)&acc[nt][0]);   // row R0: c, c+1
            float2 f1 = __half22float2(*(__half2*)&acc[nt][1]);   // row R1: c, c+1
            // local direction (rows of own band)
            float v00 = fmaf(-2.f, f0.x, sq[c]);
            float v01 = fmaf(-2.f, f0.y, sq[c + 1]);
            float v10 = fmaf(-2.f, f1.x, sq[c]);
            float v11 = fmaf(-2.f, f1.y, sq[c + 1]);
            if (v00 < t0) { int p = atomicAdd(&sm.cnt[R0], 1);
                sm.cand[R0][p] = ((unsigned long long)mono(v00) << 32) | (unsigned)(j0 + c); }
            if (v01 < t0) { int p = atomicAdd(&sm.cnt[R0], 1);
                sm.cand[R0][p] = ((unsigned long long)mono(v01) << 32) | (unsigned)(j0 + c + 1); }
            if (v10 < t1) { int p = atomicAdd(&sm.cnt[R1], 1);
                sm.cand[R1][p] = ((unsigned long long)mono(v10) << 32) | (unsigned)(j0 + c); }
            if (v11 < t1) { int p = atomicAdd(&sm.cnt[R1], 1);
                sm.cand[R1][p] = ((unsigned long long)mono(v11) << 32) | (unsigned)(j0 + c + 1); }
            // transpose direction (rows = B cols), skip on diagonal tile
            if (offdiag) {
                float w00 = fmaf(-2.f, f0.x, sqa0);
                float w01 = fmaf(-2.f, f0.y, sqa0);
                float w10 = fmaf(-2.f, f1.x, sqa1);
                float w11 = fmaf(-2.f, f1.y, sqa1);
                if (w00 <= tb[c])     try_append(j0 + c,     w00, i0 + R0);
                if (w01 <= tb[c + 1]) try_append(j0 + c + 1, w01, i0 + R0);
                if (w10 <= tb[c])     try_append(j0 + c,     w10, i0 + R1);
                if (w11 <= tb[c + 1]) try_append(j0 + c + 1, w11, i0 + R1);
            }
        }
        __syncthreads();

        if (tid < BM) {
            int n = sm.cnt[tid];
            if (n) {
                sm.cnt[tid] = 0;
                unsigned long long* bl = sm.best[tid];
                for (int q = 0; q < n; ++q) {
                    unsigned long long key = sm.cand[tid][q];
                    if (key < bl[MS - 1]) {
                        int p = MS - 1;
                        while (p > 0 && bl[p - 1] > key) { bl[p] = bl[p - 1]; --p; }
                        bl[p] = key;
                    }
                }
                sm.thr[tid] = unmono((unsigned)(bl[MS - 1] >> 32));
            }
        }
    }
    __syncthreads();

    for (int idx = tid; idx < BM * MS; idx += 256) {
        int r = idx / MS, t = idx % MS;
        g_loc[(size_t)(i0 + r) * MS + t] = sm.best[r][t];
    }
}

// ---------------- Kernel L: merge local top-24 + buffer -> top-28 per row ----------------
__global__ void sel_kernel() {
    __shared__ unsigned long long list[128][RS28];
    int tid = threadIdx.x;
    int row = blockIdx.x * 128 + tid;
    unsigned long long* bl = list[tid];
    #pragma unroll
    for (int t = 0; t < RS28; ++t) bl[t] = ULLINF;

    const unsigned long long* lp = g_loc + (size_t)row * MS;
    #pragma unroll 4
    for (int q = 0; q < MS; ++q) {
        unsigned long long key = lp[q];
        if (key < bl[RS28 - 1]) {
            int p = RS28 - 1;
            while (p > 0 && bl[p - 1] > key) { bl[p] = bl[p - 1]; --p; }
            bl[p] = key;
        }
    }
    int cnt = g_bcnt[row];
    if (cnt > CAP) cnt = CAP;
    const unsigned long long* bp = g_buf + (size_t)row * CAP;
    for (int q = 0; q < cnt; ++q) {
        unsigned long long key = bp[q];
        if (key < bl[RS28 - 1]) {
            int p = RS28 - 1;
            while (p > 0 && bl[p - 1] > key) { bl[p] = bl[p - 1]; --p; }
            bl[p] = key;
        }
    }
    #pragma unroll
    for (int t = 0; t < RS28; ++t)
        g_cand[(size_t)row * RS28 + t] = bl[t];
}

// ---------------- Kernel R: exact fp32 refine of 28 survivors -> exact top-17 ----------------
__global__ void refine_kernel(const float* __restrict__ feats) {
    int row = (blockIdx.x * blockDim.x + threadIdx.x) >> 5;
    int lane = threadIdx.x & 31;
    if (row >= NN) return;

    const float* base = feats + (size_t)row * DD;
    float4 a0 = *(const float4*)(base + lane * 4);
    float4 a1 = *(const float4*)(base + 128 + lane * 4);
    float own[8] = {a0.x, a0.y, a0.z, a0.w, a1.x, a1.y, a1.z, a1.w};

    unsigned long long mykey = ULLINF;

    #pragma unroll 4
    for (int t = 0; t < RS28; ++t) {
        unsigned long long ak = g_cand[(size_t)row * RS28 + t];
        int j = (ak == ULLINF) ? 0 : (int)(unsigned)(ak & 0xffffffffull);
        const float* nb = feats + (size_t)j * DD;
        float4 b0 = *(const float4*)(nb + lane * 4);
        float4 b1 = *(const float4*)(nb + 128 + lane * 4);
        float p = own[0]*b0.x + own[1]*b0.y + own[2]*b0.z + own[3]*b0.w
                + own[4]*b1.x + own[5]*b1.y + own[6]*b1.z + own[7]*b1.w;
        #pragma unroll
        for (int o = 16; o; o >>= 1) p += __shfl_xor_sync(0xffffffffu, p, o);
        float val = fmaf(-2.f, p, g_sq[j]);
        unsigned long long key = (ak == ULLINF) ? ULLINF
                               : (((unsigned long long)mono(val) << 32) | (unsigned)j);
        if (lane == t) mykey = key;
    }

    int rank = 0;
    #pragma unroll
    for (int s = 0; s < RS28; ++s) {
        unsigned long long ok = __shfl_sync(0xffffffffu, mykey, s);
        rank += (ok < mykey);
    }
    if (lane < RS28 && rank < KSEL && mykey != ULLINF)
        g_best[(size_t)row * KSEL + rank] = mykey;
}

// ---------------- Kernel C: mutual mask + sparse softmax + AV + residual + normalize ----------------
__global__ void fuse_kernel(const float* __restrict__ feats, float* __restrict__ out) {
    int gw = (blockIdx.x * blockDim.x + threadIdx.x) >> 5;
    int lane = threadIdx.x & 31;
    if (gw >= NN) return;
    const int row = gw;
    const float* base = feats + (size_t)row * DD;
    float4 a0 = *(const float4*)(base + lane * 4);
    float4 a1 = *(const float4*)(base + 128 + lane * 4);
    float own[8] = {a0.x, a0.y, a0.z, a0.w, a1.x, a1.y, a1.z, a1.w};

    int my_nbr = -1;
    int cnt = 0;
    #pragma unroll
    for (int t = 0; t < KSEL; ++t) {
        unsigned long long key = g_best[(size_t)row * KSEL + t];
        int j = (int)(unsigned)(key & 0xffffffffull);
        if (j != row && cnt < KK) {
            if (cnt == lane) my_nbr = j;
            cnt++;
        }
    }

    bool found = false;
    if (lane < KK && my_nbr >= 0) {
        #pragma unroll
        for (int t = 0; t < KSEL; ++t) {
            unsigned long long key = g_best[(size_t)my_nbr * KSEL + t];
            if ((int)(unsigned)(key & 0xffffffffull) == row) found = true;
        }
    }
    unsigned mmask = __ballot_sync(0xffffffffu, found) & 0xffffu;

    float m = 1.0f, Z = 1.0f;
    float acc[8];
    #pragma unroll
    for (int e = 0; e < 8; ++e) acc[e] = own[e];

    for (int l = 0; l < KK; ++l) {
        if (!((mmask >> l) & 1u)) continue;
        int j = __shfl_sync(0xffffffffu, my_nbr, l);
        const float* nb = feats + (size_t)j * DD;
        float4 b0 = *(const float4*)(nb + lane * 4);
        float4 b1 = *(const float4*)(nb + 128 + lane * 4);
        float v[8] = {b0.x, b0.y, b0.z, b0.w, b1.x, b1.y, b1.z, b1.w};
        float p = 0.f;
        #pragma unroll
        for (int e = 0; e < 8; ++e) p = fmaf(own[e], v[e], p);
        #pragma unroll
        for (int o = 16; o; o >>= 1) p += __shfl_xor_sync(0xffffffffu, p, o);
        if (p > m) {
            float f = expf(m - p);
            Z = Z * f + 1.0f;
            #pragma unroll
            for (int e = 0; e < 8; ++e) acc[e] = fmaf(acc[e], f, v[e]);
            m = p;
        } else {
            float wgt = expf(p - m);
            Z += wgt;
            #pragma unroll
            for (int e = 0; e < 8; ++e) acc[e] = fmaf(wgt, v[e], acc[e]);
        }
    }

    float invZ = 1.0f / Z;
    float fcm[8];
    float ss = 0.f;
    #pragma unroll
    for (int e = 0; e < 8; ++e) {
        fcm[e] = fmaf(acc[e], invZ, own[e]);
        ss = fmaf(fcm[e], fcm[e], ss);
    }
    #pragma unroll
    for (int o = 16; o; o >>= 1) ss += __shfl_xor_sync(0xffffffffu, ss, o);
    float inv = 1.0f / fmaxf(sqrtf(ss), 1e-12f);

    float* op = out + (size_t)row * DD;
    *(float4*)(op + lane * 4)       = make_float4(fcm[0]*inv, fcm[1]*inv, fcm[2]*inv, fcm[3]*inv);
    *(float4*)(op + 128 + lane * 4) = make_float4(fcm[4]*inv, fcm[5]*inv, fcm[6]*inv, fcm[7]*inv);
}

// ---------------- launch ----------------
extern "C" void kernel_launch(void* const* d_in, const int* in_sizes, int n_in,
                              void* d_out, int out_size) {
    const float* feats = (const float*)d_in[0];
    float* out = (float*)d_out;
    (void)in_sizes; (void)n_in; (void)out_size;

    cudaFuncSetAttribute(thresh_kernel, cudaFuncAttributeMaxDynamicSharedMemorySize,
                         (int)sizeof(SmemT));
    cudaFuncSetAttribute(screen_kernel, cudaFuncAttributeMaxDynamicSharedMemorySize,
                         (int)sizeof(SmemS));

    sq_kernel<<<NN / 8, 256>>>(feats);
    thresh_kernel<<<NN / BM, 256, sizeof(SmemT)>>>();
    screen_kernel<<<NTILE, 256, sizeof(SmemS)>>>();
    sel_kernel<<<NN / 128, 128>>>();
    refine_kernel<<<NN / 8, 256>>>(feats);
    fuse_kernel<<<NN / 8, 256>>>(feats, out);
}

// round 11
// speedup vs baseline: 1.4400x; 1.4400x over previous
#include <cuda_runtime.h>
#include <cuda_fp16.h>
#include <math.h>

#define NN 8192
#define DD 256
#define KK 16
#define KSEL 17
#define RS28 28           // refine candidates per row
#define MS 24             // local streaming top-M per row
#define BM 64
#define BN 64
#define NTILE 128         // 8192/64
#define JTS 8             // thresh-pass sample tiles (512 cols)
#define MST 20            // thresh-pass top-M -> tau
#define RSB 264           // smem row stride in fp16 elements (528B)
#define CAP 1024
#define TCAP 512          // per-tile transpose staging capacity
#define SCAP 384          // per-row buffer scan cap in sel (exp 160, +17 sigma)
#define ULLINF 0xFFFFFFFFFFFFFFFFull

__device__ float g_sq[NN];
__device__ float g_tau[NN];
__device__ __half2 g_fh16[NN * DD / 2];
__device__ int g_bcnt[NN];
__device__ unsigned long long g_buf[(size_t)NN * CAP];
__device__ unsigned long long g_loc[(size_t)NN * MS];
__device__ unsigned long long g_cand[NN * RS28];
__device__ unsigned long long g_best[NN * KSEL];

__device__ __forceinline__ unsigned smem_u32(const void* p) {
    unsigned a;
    asm("{ .reg .u64 t; cvta.to.shared.u64 t, %1; cvt.u32.u64 %0, t; }" : "=r"(a) : "l"(p));
    return a;
}
__device__ __forceinline__ unsigned mono(float f) {
    unsigned u = __float_as_uint(f);
    return (u & 0x80000000u) ? ~u : (u | 0x80000000u);
}
__device__ __forceinline__ float unmono(unsigned u) {
    return __uint_as_float((u & 0x80000000u) ? (u ^ 0x80000000u) : ~u);
}

#define CP16(dst, src) asm volatile("cp.async.cg.shared.global [%0], [%1], 16;" :: "r"(dst), "l"(src) : "memory")
#define CP_COMMIT()    asm volatile("cp.async.commit_group;" ::: "memory")
#define CP_WAIT(n)     asm volatile("cp.async.wait_group %0;" :: "n"(n) : "memory")
#define LDSM_X4(r0, r1, r2, r3, a) \
    asm volatile("ldmatrix.sync.aligned.m8n8.x4.shared.b16 {%0,%1,%2,%3}, [%4];" \
        : "=r"(r0), "=r"(r1), "=r"(r2), "=r"(r3) : "r"(a))
#define MMA_F16(d0, d1, a0, a1, a2, a3, b0, b1) \
    asm volatile("mma.sync.aligned.m16n8k16.row.col.f16.f16.f16.f16 " \
        "{%0,%1},{%2,%3,%4,%5},{%6,%7},{%0,%1};" \
        : "+r"(d0), "+r"(d1) \
        : "r"(a0), "r"(a1), "r"(a2), "r"(a3), "r"(b0), "r"(b1))

// ---------------- Kernel A: norms + fp16 convert + counter reset ----------------
__global__ void sq_kernel(const float* __restrict__ feats) {
    int gw = (blockIdx.x * blockDim.x + threadIdx.x) >> 5;
    int lane = threadIdx.x & 31;
    if (gw >= NN) return;
    const float4* rowp = (const float4*)(feats + (size_t)gw * DD);
    float4 a = rowp[lane];
    float4 b = rowp[lane + 32];
    float s = a.x*a.x + a.y*a.y + a.z*a.z + a.w*a.w
            + b.x*b.x + b.y*b.y + b.z*b.z + b.w*b.w;
    #pragma unroll
    for (int o = 16; o; o >>= 1) s += __shfl_xor_sync(0xffffffffu, s, o);
    if (lane == 0) { g_sq[gw] = s; g_bcnt[gw] = 0; }
    __half2* dst = g_fh16 + (size_t)gw * (DD / 2);
    dst[lane * 2]          = __floats2half2_rn(a.x, a.y);
    dst[lane * 2 + 1]      = __floats2half2_rn(a.z, a.w);
    dst[64 + lane * 2]     = __floats2half2_rn(b.x, b.y);
    dst[64 + lane * 2 + 1] = __floats2half2_rn(b.z, b.w);
}

// ---------------- Kernel T: sample 512 cols -> per-row tau (20th-smallest key) ----------------
struct SmemT {
    __half A[BM][RSB];
    __half B[2][BN][RSB];
    float sqB[2][BN];
    float thr[BM];
    int   cnt[BM];
    unsigned long long best[BM][MST];
    unsigned long long cand[BM][BN];
};

__device__ __forceinline__ void prefetch_BT(SmemT& sm, int s, int j0, int tid) {
    #pragma unroll
    for (int t = 0; t < 8; ++t) {
        int idx = t * 256 + tid;
        int r = idx >> 5, ch = idx & 31;
        unsigned dst = smem_u32(&sm.B[s][r][ch * 8]);
        const void* src = (const char*)g_fh16 + (((size_t)(j0 + r) * DD) + ch * 8) * 2;
        CP16(dst, src);
    }
    if (tid < 16) {
        unsigned dst = smem_u32(&sm.sqB[s][tid * 4]);
        const void* src = g_sq + j0 + tid * 4;
        CP16(dst, src);
    }
}

__global__ void __launch_bounds__(256, 1) thresh_kernel() {
    extern __shared__ char raw[];
    SmemT& sm = *reinterpret_cast<SmemT*>(raw);
    const int tid = threadIdx.x;
    const int lane = tid & 31;
    const int w = tid >> 5;
    const int wr = w >> 1;
    const int wc = w & 1;
    const int i0 = blockIdx.x * BM;

    #pragma unroll
    for (int t = 0; t < 8; ++t) {
        int idx = t * 256 + tid;
        int r = idx >> 5, ch = idx & 31;
        unsigned dst = smem_u32(&sm.A[r][ch * 8]);
        const void* src = (const char*)g_fh16 + (((size_t)(i0 + r) * DD) + ch * 8) * 2;
        CP16(dst, src);
    }
    CP_COMMIT();
    prefetch_BT(sm, 0, 0, tid);
    CP_COMMIT();

    if (tid < BM) {
        sm.thr[tid] = __int_as_float(0x7f800000);
        sm.cnt[tid] = 0;
        #pragma unroll
        for (int t = 0; t < MST; ++t) sm.best[tid][t] = 0xFF800000FFFFFFFFull;
    }

    const unsigned aAddr = smem_u32(&sm.A[wr * 16 + (lane & 15)][0]) + ((lane >> 4) << 4);
    const int rowB = wc * 32 + ((lane >> 4) << 3) + (lane & 7);
    const unsigned bColOff = ((lane >> 3) & 1) << 4;
    unsigned bAddrBase[2];
    bAddrBase[0] = smem_u32(&sm.B[0][rowB][0]) + bColOff;
    bAddrBase[1] = smem_u32(&sm.B[1][rowB][0]) + bColOff;

    const int R0 = wr * 16 + (lane >> 2);
    const int R1 = R0 + 8;
    const int cBase = wc * 32 + 2 * (lane & 3);

    for (int jt = 0; jt < JTS; ++jt) {
        const int s = jt & 1;
        const int j0 = jt * BN;

        if (jt + 1 < JTS) {
            prefetch_BT(sm, s ^ 1, (jt + 1) * BN, tid);
            CP_COMMIT();
            CP_WAIT(1);
        } else {
            CP_WAIT(0);
        }
        __syncthreads();

        unsigned acc[4][2];
        #pragma unroll
        for (int nt = 0; nt < 4; ++nt) { acc[nt][0] = 0u; acc[nt][1] = 0u; }

        const unsigned bA = bAddrBase[s];
        #pragma unroll
        for (int ks = 0; ks < 16; ++ks) {
            unsigned a0, a1, a2, a3;
            LDSM_X4(a0, a1, a2, a3, aAddr + ks * 32);
            unsigned p00, p01, p10, p11, q00, q01, q10, q11;
            LDSM_X4(p00, p01, p10, p11, bA + ks * 32);
            LDSM_X4(q00, q01, q10, q11, bA + 16 * (RSB * 2) + ks * 32);
            MMA_F16(acc[0][0], acc[0][1], a0, a1, a2, a3, p00, p01);
            MMA_F16(acc[1][0], acc[1][1], a0, a1, a2, a3, p10, p11);
            MMA_F16(acc[2][0], acc[2][1], a0, a1, a2, a3, q00, q01);
            MMA_F16(acc[3][0], acc[3][1], a0, a1, a2, a3, q10, q11);
        }

        const float t0 = sm.thr[R0];
        const float t1 = sm.thr[R1];
        const float* sq = sm.sqB[s];
        #pragma unroll
        for (int nt = 0; nt < 4; ++nt) {
            const int c = cBase + nt * 8;
            float2 f0 = __half22float2(*(__half2*)&acc[nt][0]);
            float2 f1 = __half22float2(*(__half2*)&acc[nt][1]);
            float v00 = fmaf(-2.f, f0.x, sq[c]);
            float v01 = fmaf(-2.f, f0.y, sq[c + 1]);
            float v10 = fmaf(-2.f, f1.x, sq[c]);
            float v11 = fmaf(-2.f, f1.y, sq[c + 1]);
            if (v00 < t0) { int p = atomicAdd(&sm.cnt[R0], 1);
                sm.cand[R0][p] = ((unsigned long long)mono(v00) << 32) | (unsigned)(j0 + c); }
            if (v01 < t0) { int p = atomicAdd(&sm.cnt[R0], 1);
                sm.cand[R0][p] = ((unsigned long long)mono(v01) << 32) | (unsigned)(j0 + c + 1); }
            if (v10 < t1) { int p = atomicAdd(&sm.cnt[R1], 1);
                sm.cand[R1][p] = ((unsigned long long)mono(v10) << 32) | (unsigned)(j0 + c); }
            if (v11 < t1) { int p = atomicAdd(&sm.cnt[R1], 1);
                sm.cand[R1][p] = ((unsigned long long)mono(v11) << 32) | (unsigned)(j0 + c + 1); }
        }
        __syncthreads();

        if (tid < BM) {
            int n = sm.cnt[tid];
            if (n) {
                sm.cnt[tid] = 0;
                unsigned long long* bl = sm.best[tid];
                for (int q = 0; q < n; ++q) {
                    unsigned long long key = sm.cand[tid][q];
                    if (key < bl[MST - 1]) {
                        int p = MST - 1;
                        while (p > 0 && bl[p - 1] > key) { bl[p] = bl[p - 1]; --p; }
                        bl[p] = key;
                    }
                }
                sm.thr[tid] = unmono((unsigned)(bl[MST - 1] >> 32));
            }
        }
    }

    if (tid < BM)
        g_tau[i0 + tid] = unmono((unsigned)(sm.best[tid][MST - 1] >> 32));
}

// ---------------- Kernel S: balanced cyclic symmetric screen (batched appends) ----------------
struct SmemS {
    __half A[BM][RSB];
    __half B[2][BN][RSB];
    float sqB[2][BN], tauB[2][BN];
    float sqA[BM];
    float thr[BM];
    int   cnt[BM];
    unsigned long long best[BM][MS];
    unsigned long long cand[BM][BN];
    unsigned long long tval[TCAP];
    unsigned char tcol[TCAP];
    int tcnt;
};

__device__ __forceinline__ void prefetch_BS(SmemS& sm, int s, int j0, int tid) {
    #pragma unroll
    for (int t = 0; t < 8; ++t) {
        int idx = t * 256 + tid;
        int r = idx >> 5, ch = idx & 31;
        unsigned dst = smem_u32(&sm.B[s][r][ch * 8]);
        const void* src = (const char*)g_fh16 + (((size_t)(j0 + r) * DD) + ch * 8) * 2;
        CP16(dst, src);
    }
    if (tid < 16) {
        unsigned dst = smem_u32(&sm.sqB[s][tid * 4]);
        CP16(dst, (const void*)(g_sq + j0 + tid * 4));
    } else if (tid < 32) {
        int t = tid - 16;
        unsigned dst = smem_u32(&sm.tauB[s][t * 4]);
        CP16(dst, (const void*)(g_tau + j0 + t * 4));
    }
}

__device__ __forceinline__ void stage_t(SmemS& sm, float v, int c, int srcRow) {
    unsigned long long val = ((unsigned long long)mono(v) << 32) | (unsigned)srcRow;
    int p = atomicAdd(&sm.tcnt, 1);
    if (p < TCAP) {
        sm.tval[p] = val;
        sm.tcol[p] = (unsigned char)c;
    } else {
        // overflow fallback (astronomically rare): direct append
        int trow_p = atomicAdd(&g_bcnt[/*computed by caller's j0 + c*/ 0], 0); // placeholder avoided
        (void)trow_p;
    }
}

__global__ void __launch_bounds__(256, 1) screen_kernel() {
    extern __shared__ char raw[];
    SmemS& sm = *reinterpret_cast<SmemS*>(raw);
    const int tid = threadIdx.x;
    const int lane = tid & 31;
    const int w = tid >> 5;
    const int wr = w >> 1;
    const int wc = w & 1;
    const int it = blockIdx.x;
    const int i0 = it * BM;
    const int NT = (it < 64) ? 65 : 64;

    #pragma unroll
    for (int t = 0; t < 8; ++t) {
        int idx = t * 256 + tid;
        int r = idx >> 5, ch = idx & 31;
        unsigned dst = smem_u32(&sm.A[r][ch * 8]);
        const void* src = (const char*)g_fh16 + (((size_t)(i0 + r) * DD) + ch * 8) * 2;
        CP16(dst, src);
    }
    CP_COMMIT();
    prefetch_BS(sm, 0, i0, tid);
    CP_COMMIT();

    if (tid < BM) {
        sm.sqA[tid] = g_sq[i0 + tid];
        sm.thr[tid] = __int_as_float(0x7f800000);
        sm.cnt[tid] = 0;
        #pragma unroll
        for (int t = 0; t < MS; ++t) sm.best[tid][t] = 0xFF800000FFFFFFFFull;
    }
    if (tid == 0) sm.tcnt = 0;

    const unsigned aAddr = smem_u32(&sm.A[wr * 16 + (lane & 15)][0]) + ((lane >> 4) << 4);
    const int rowB = wc * 32 + ((lane >> 4) << 3) + (lane & 7);
    const unsigned bColOff = ((lane >> 3) & 1) << 4;
    unsigned bAddrBase[2];
    bAddrBase[0] = smem_u32(&sm.B[0][rowB][0]) + bColOff;
    bAddrBase[1] = smem_u32(&sm.B[1][rowB][0]) + bColOff;

    const int R0 = wr * 16 + (lane >> 2);
    const int R1 = R0 + 8;
    const int cBase = wc * 32 + 2 * (lane & 3);

    for (int t = 0; t < NT; ++t) {
        const int s = t & 1;
        const int jt = (it + t) & (NTILE - 1);
        const int j0 = jt * BN;
        const bool offdiag = (t != 0);

        if (t + 1 < NT) {
            prefetch_BS(sm, s ^ 1, ((it + t + 1) & (NTILE - 1)) * BN, tid);
            CP_COMMIT();
            CP_WAIT(1);
        } else {
            CP_WAIT(0);
        }
        __syncthreads();   // B[s]+sq/tau visible; prev flush + tcnt reset visible

        unsigned acc[4][2];
        #pragma unroll
        for (int nt = 0; nt < 4; ++nt) { acc[nt][0] = 0u; acc[nt][1] = 0u; }

        const unsigned bA = bAddrBase[s];
        #pragma unroll
        for (int ks = 0; ks < 16; ++ks) {
            unsigned a0, a1, a2, a3;
            LDSM_X4(a0, a1, a2, a3, aAddr + ks * 32);
            unsigned p00, p01, p10, p11, q00, q01, q10, q11;
            LDSM_X4(p00, p01, p10, p11, bA + ks * 32);
            LDSM_X4(q00, q01, q10, q11, bA + 16 * (RSB * 2) + ks * 32);
            MMA_F16(acc[0][0], acc[0][1], a0, a1, a2, a3, p00, p01);
            MMA_F16(acc[1][0], acc[1][1], a0, a1, a2, a3, p10, p11);
            MMA_F16(acc[2][0], acc[2][1], a0, a1, a2, a3, q00, q01);
            MMA_F16(acc[3][0], acc[3][1], a0, a1, a2, a3, q10, q11);
        }

        const float t0 = sm.thr[R0];
        const float t1 = sm.thr[R1];
        const float sqa0 = sm.sqA[R0];
        const float sqa1 = sm.sqA[R1];
        const float* sq = sm.sqB[s];
        const float* tb = sm.tauB[s];
        #pragma unroll
        for (int nt = 0; nt < 4; ++nt) {
            const int c = cBase + nt * 8;
            float2 f0 = __half22float2(*(__half2*)&acc[nt][0]);
            float2 f1 = __half22float2(*(__half2*)&acc[nt][1]);
            float v00 = fmaf(-2.f, f0.x, sq[c]);
            float v01 = fmaf(-2.f, f0.y, sq[c + 1]);
            float v10 = fmaf(-2.f, f1.x, sq[c]);
            float v11 = fmaf(-2.f, f1.y, sq[c + 1]);
            if (v00 < t0) { int p = atomicAdd(&sm.cnt[R0], 1);
                sm.cand[R0][p] = ((unsigned long long)mono(v00) << 32) | (unsigned)(j0 + c); }
            if (v01 < t0) { int p = atomicAdd(&sm.cnt[R0], 1);
                sm.cand[R0][p] = ((unsigned long long)mono(v01) << 32) | (unsigned)(j0 + c + 1); }
            if (v10 < t1) { int p = atomicAdd(&sm.cnt[R1], 1);
                sm.cand[R1][p] = ((unsigned long long)mono(v10) << 32) | (unsigned)(j0 + c); }
            if (v11 < t1) { int p = atomicAdd(&sm.cnt[R1], 1);
                sm.cand[R1][p] = ((unsigned long long)mono(v11) << 32) | (unsigned)(j0 + c + 1); }
            if (offdiag) {
                float w00 = fmaf(-2.f, f0.x, sqa0);
                float w01 = fmaf(-2.f, f0.y, sqa0);
                float w10 = fmaf(-2.f, f1.x, sqa1);
                float w11 = fmaf(-2.f, f1.y, sqa1);
                // stage into shared buffer (fast path); overflow -> direct global
                if (w00 <= tb[c]) {
                    int p = atomicAdd(&sm.tcnt, 1);
                    if (p < TCAP) { sm.tval[p] = ((unsigned long long)mono(w00) << 32) | (unsigned)(i0 + R0); sm.tcol[p] = (unsigned char)c; }
                    else { int g = atomicAdd(&g_bcnt[j0 + c], 1); if (g < CAP) g_buf[(size_t)(j0 + c) * CAP + g] = ((unsigned long long)mono(w00) << 32) | (unsigned)(i0 + R0); }
                }
                if (w01 <= tb[c + 1]) {
                    int p = atomicAdd(&sm.tcnt, 1);
                    if (p < TCAP) { sm.tval[p] = ((unsigned long long)mono(w01) << 32) | (unsigned)(i0 + R0); sm.tcol[p] = (unsigned char)(c + 1); }
                    else { int g = atomicAdd(&g_bcnt[j0 + c + 1], 1); if (g < CAP) g_buf[(size_t)(j0 + c + 1) * CAP + g] = ((unsigned long long)mono(w01) << 32) | (unsigned)(i0 + R0); }
                }
                if (w10 <= tb[c]) {
                    int p = atomicAdd(&sm.tcnt, 1);
                    if (p < TCAP) { sm.tval[p] = ((unsigned long long)mono(w10) << 32) | (unsigned)(i0 + R1); sm.tcol[p] = (unsigned char)c; }
                    else { int g = atomicAdd(&g_bcnt[j0 + c], 1); if (g < CAP) g_buf[(size_t)(j0 + c) * CAP + g] = ((unsigned long long)mono(w10) << 32) | (unsigned)(i0 + R1); }
                }
                if (w11 <= tb[c + 1]) {
                    int p = atomicAdd(&sm.tcnt, 1);
                    if (p < TCAP) { sm.tval[p] = ((unsigned long long)mono(w11) << 32) | (unsigned)(i0 + R1); sm.tcol[p] = (unsigned char)(c + 1); }
                    else { int g = atomicAdd(&g_bcnt[j0 + c + 1], 1); if (g < CAP) g_buf[(size_t)(j0 + c + 1) * CAP + g] = ((unsigned long long)mono(w11) << 32) | (unsigned)(i0 + R1); }
                }
            }
        }
        __syncthreads();   // epilogue complete: tcnt/tval/tcol and cand/cnt stable

        // cooperative drain of staged transpose appends (independent atomics across threads)
        {
            int n = sm.tcnt;
            if (n > TCAP) n = TCAP;
            for (int q = tid; q < n; q += 256) {
                int trow = j0 + (int)sm.tcol[q];
                int p = atomicAdd(&g_bcnt[trow], 1);
                if (p < CAP) g_buf[(size_t)trow * CAP + p] = sm.tval[q];
            }
        }
        // local flush (tid<BM) runs concurrently with the drain
        if (tid < BM) {
            int n = sm.cnt[tid];
            if (n) {
                sm.cnt[tid] = 0;
                unsigned long long* bl = sm.best[tid];
                for (int q = 0; q < n; ++q) {
                    unsigned long long key = sm.cand[tid][q];
                    if (key < bl[MS - 1]) {
                        int p = MS - 1;
                        while (p > 0 && bl[p - 1] > key) { bl[p] = bl[p - 1]; --p; }
                        bl[p] = key;
                    }
                }
                sm.thr[tid] = unmono((unsigned)(bl[MS - 1] >> 32));
            }
        }
        __syncthreads();   // drain + flush complete
        if (tid == 0) sm.tcnt = 0;
        // loop-top barrier orders the reset before next epilogue
    }
    __syncthreads();

    for (int idx = tid; idx < BM * MS; idx += 256) {
        int r = idx / MS, t = idx % MS;
        g_loc[(size_t)(i0 + r) * MS + t] = sm.best[r][t];
    }
}

// ---------------- Kernel L: warp-per-row merge of local top-24 + buffer -> top-28 ----------------
__global__ void __launch_bounds__(256) sel_kernel() {
    __shared__ unsigned long long ch[8][32][13];
    const int lane = threadIdx.x & 31;
    const int w = threadIdx.x >> 5;
    const int row = blockIdx.x * 8 + w;

    unsigned long long* my = ch[w][lane];
    int len = 0;
    // one local entry per lane (lanes 0..23)
    if (lane < MS) { my[0] = g_loc[(size_t)row * MS + lane]; len = 1; }
    // strided buffer entries, insertion-sorted into private chunk
    int cnt = g_bcnt[row];
    if (cnt > SCAP) cnt = SCAP;
    const unsigned long long* bp = g_buf + (size_t)row * CAP;
    for (int q = lane; q < cnt; q += 32) {
        unsigned long long key = bp[q];
        int p = len++;
        while (p > 0 && my[p - 1] > key) { my[p] = my[p - 1]; --p; }
        my[p] = key;
    }
    __syncwarp();

    // 28 warp-min head extractions
    int ptr = 0;
    for (int sel = 0; sel < RS28; ++sel) {
        unsigned long long h = (ptr < len) ? my[ptr] : ULLINF;
        unsigned long long M = h;
        #pragma unroll
        for (int o = 16; o; o >>= 1) {
            unsigned long long v = __shfl_xor_sync(0xffffffffu, M, o);
            M = (v < M) ? v : M;
        }
        unsigned b = __ballot_sync(0xffffffffu, h == M);
        if (lane == (__ffs(b) - 1)) ++ptr;
        if (lane == 0) g_cand[(size_t)row * RS28 + sel] = M;
    }
}

// ---------------- Kernel R: exact fp32 refine of 28 survivors -> exact top-17 ----------------
__global__ void refine_kernel(const float* __restrict__ feats) {
    int row = (blockIdx.x * blockDim.x + threadIdx.x) >> 5;
    int lane = threadIdx.x & 31;
    if (row >= NN) return;

    const float* base = feats + (size_t)row * DD;
    float4 a0 = *(const float4*)(base + lane * 4);
    float4 a1 = *(const float4*)(base + 128 + lane * 4);
    float own[8] = {a0.x, a0.y, a0.z, a0.w, a1.x, a1.y, a1.z, a1.w};

    unsigned long long mykey = ULLINF;

    #pragma unroll 4
    for (int t = 0; t < RS28; ++t) {
        unsigned long long ak = g_cand[(size_t)row * RS28 + t];
        int j = (ak == ULLINF) ? 0 : (int)(unsigned)(ak & 0xffffffffull);
        const float* nb = feats + (size_t)j * DD;
        float4 b0 = *(const float4*)(nb + lane * 4);
        float4 b1 = *(const float4*)(nb + 128 + lane * 4);
        float p = own[0]*b0.x + own[1]*b0.y + own[2]*b0.z + own[3]*b0.w
                + own[4]*b1.x + own[5]*b1.y + own[6]*b1.z + own[7]*b1.w;
        #pragma unroll
        for (int o = 16; o; o >>= 1) p += __shfl_xor_sync(0xffffffffu, p, o);
        float val = fmaf(-2.f, p, g_sq[j]);
        unsigned long long key = (ak == ULLINF) ? ULLINF
                               : (((unsigned long long)mono(val) << 32) | (unsigned)j);
        if (lane == t) mykey = key;
    }

    int rank = 0;
    #pragma unroll
    for (int s = 0; s < RS28; ++s) {
        unsigned long long ok = __shfl_sync(0xffffffffu, mykey, s);
        rank += (ok < mykey);
    }
    if (lane < RS28 && rank < KSEL && mykey != ULLINF)
        g_best[(size_t)row * KSEL + rank] = mykey;
}

// ---------------- Kernel C: mutual mask + sparse softmax + AV + residual + normalize ----------------
__global__ void fuse_kernel(const float* __restrict__ feats, float* __restrict__ out) {
    int gw = (blockIdx.x * blockDim.x + threadIdx.x) >> 5;
    int lane = threadIdx.x & 31;
    if (gw >= NN) return;
    const int row = gw;
    const float* base = feats + (size_t)row * DD;
    float4 a0 = *(const float4*)(base + lane * 4);
    float4 a1 = *(const float4*)(base + 128 + lane * 4);
    float own[8] = {a0.x, a0.y, a0.z, a0.w, a1.x, a1.y, a1.z, a1.w};

    int my_nbr = -1;
    int cnt = 0;
    #pragma unroll
    for (int t = 0; t < KSEL; ++t) {
        unsigned long long key = g_best[(size_t)row * KSEL + t];
        int j = (int)(unsigned)(key & 0xffffffffull);
        if (j != row && cnt < KK) {
            if (cnt == lane) my_nbr = j;
            cnt++;
        }
    }

    bool found = false;
    if (lane < KK && my_nbr >= 0) {
        #pragma unroll
        for (int t = 0; t < KSEL; ++t) {
            unsigned long long key = g_best[(size_t)my_nbr * KSEL + t];
            if ((int)(unsigned)(key & 0xffffffffull) == row) found = true;
        }
    }
    unsigned mmask = __ballot_sync(0xffffffffu, found) & 0xffffu;

    float m = 1.0f, Z = 1.0f;
    float acc[8];
    #pragma unroll
    for (int e = 0; e < 8; ++e) acc[e] = own[e];

    for (int l = 0; l < KK; ++l) {
        if (!((mmask >> l) & 1u)) continue;
        int j = __shfl_sync(0xffffffffu, my_nbr, l);
        const float* nb = feats + (size_t)j * DD;
        float4 b0 = *(const float4*)(nb + lane * 4);
        float4 b1 = *(const float4*)(nb + 128 + lane * 4);
        float v[8] = {b0.x, b0.y, b0.z, b0.w, b1.x, b1.y, b1.z, b1.w};
        float p = 0.f;
        #pragma unroll
        for (int e = 0; e < 8; ++e) p = fmaf(own[e], v[e], p);
        #pragma unroll
        for (int o = 16; o; o >>= 1) p += __shfl_xor_sync(0xffffffffu, p, o);
        if (p > m) {
            float f = expf(m - p);
            Z = Z * f + 1.0f;
            #pragma unroll
            for (int e = 0; e < 8; ++e) acc[e] = fmaf(acc[e], f, v[e]);
            m = p;
        } else {
            float wgt = expf(p - m);
            Z += wgt;
            #pragma unroll
            for (int e = 0; e < 8; ++e) acc[e] = fmaf(wgt, v[e], acc[e]);
        }
    }

    float invZ = 1.0f / Z;
    float fcm[8];
    float ss = 0.f;
    #pragma unroll
    for (int e = 0; e < 8; ++e) {
        fcm[e] = fmaf(acc[e], invZ, own[e]);
        ss = fmaf(fcm[e], fcm[e], ss);
    }
    #pragma unroll
    for (int o = 16; o; o >>= 1) ss += __shfl_xor_sync(0xffffffffu, ss, o);
    float inv = 1.0f / fmaxf(sqrtf(ss), 1e-12f);

    float* op = out + (size_t)row * DD;
    *(float4*)(op + lane * 4)       = make_float4(fcm[0]*inv, fcm[1]*inv, fcm[2]*inv, fcm[3]*inv);
    *(float4*)(op + 128 + lane * 4) = make_float4(fcm[4]*inv, fcm[5]*inv, fcm[6]*inv, fcm[7]*inv);
}

// ---------------- launch ----------------
extern "C" void kernel_launch(void* const* d_in, const int* in_sizes, int n_in,
                              void* d_out, int out_size) {
    const float* feats = (const float*)d_in[0];
    float* out = (float*)d_out;
    (void)in_sizes; (void)n_in; (void)out_size;

    cudaFuncSetAttribute(thresh_kernel, cudaFuncAttributeMaxDynamicSharedMemorySize,
                         (int)sizeof(SmemT));
    cudaFuncSetAttribute(screen_kernel, cudaFuncAttributeMaxDynamicSharedMemorySize,
                         (int)sizeof(SmemS));

    sq_kernel<<<NN / 8, 256>>>(feats);
    thresh_kernel<<<NN / BM, 256, sizeof(SmemT)>>>();
    screen_kernel<<<NTILE, 256, sizeof(SmemS)>>>();
    sel_kernel<<<NN / 8, 256>>>();
    refine_kernel<<<NN / 8, 256>>>(feats);
    fuse_kernel<<<NN / 8, 256>>>(feats, out);
}

// round 12
// speedup vs baseline: 1.5571x; 1.0813x over previous
#include <cuda_runtime.h>
#include <cuda_fp16.h>
#include <math.h>

#define NN 8192
#define DD 256
#define KK 16
#define KSEL 17
#define RS28 28           // refine candidates per row
#define MS 24             // local streaming top-M per row
#define BM 64
#define BN 64
#define NTILE 128         // 8192/64
#define JTS 8             // thresh-pass sample tiles (512 cols)
#define MST 20            // thresh-pass top-M -> tau
#define RSB 264           // smem row stride in fp16 elements (528B)
#define CAP 1024
#define TCAP 512          // per-tile transpose staging capacity
#define SCAP 384          // per-row buffer scan cap in sel
#define STH 512           // screen kernel threads (16 warps -> 4/SMSP)
#define ULLINF 0xFFFFFFFFFFFFFFFFull

__device__ float g_sq[NN];
__device__ float g_tau[NN];
__device__ __half2 g_fh16[NN * DD / 2];
__device__ int g_bcnt[NN];
__device__ unsigned long long g_buf[(size_t)NN * CAP];
__device__ unsigned long long g_loc[(size_t)NN * MS];
__device__ unsigned long long g_cand[NN * RS28];
__device__ unsigned long long g_best[NN * KSEL];

__device__ __forceinline__ unsigned smem_u32(const void* p) {
    unsigned a;
    asm("{ .reg .u64 t; cvta.to.shared.u64 t, %1; cvt.u32.u64 %0, t; }" : "=r"(a) : "l"(p));
    return a;
}
__device__ __forceinline__ unsigned mono(float f) {
    unsigned u = __float_as_uint(f);
    return (u & 0x80000000u) ? ~u : (u | 0x80000000u);
}
__device__ __forceinline__ float unmono(unsigned u) {
    return __uint_as_float((u & 0x80000000u) ? (u ^ 0x80000000u) : ~u);
}

#define CP16(dst, src) asm volatile("cp.async.cg.shared.global [%0], [%1], 16;" :: "r"(dst), "l"(src) : "memory")
#define CP_COMMIT()    asm volatile("cp.async.commit_group;" ::: "memory")
#define CP_WAIT(n)     asm volatile("cp.async.wait_group %0;" :: "n"(n) : "memory")
#define LDSM_X4(r0, r1, r2, r3, a) \
    asm volatile("ldmatrix.sync.aligned.m8n8.x4.shared.b16 {%0,%1,%2,%3}, [%4];" \
        : "=r"(r0), "=r"(r1), "=r"(r2), "=r"(r3) : "r"(a))
#define MMA_F16(d0, d1, a0, a1, a2, a3, b0, b1) \
    asm volatile("mma.sync.aligned.m16n8k16.row.col.f16.f16.f16.f16 " \
        "{%0,%1},{%2,%3,%4,%5},{%6,%7},{%0,%1};" \
        : "+r"(d0), "+r"(d1) \
        : "r"(a0), "r"(a1), "r"(a2), "r"(a3), "r"(b0), "r"(b1))

// ---------------- Kernel A: norms + fp16 convert + counter reset ----------------
__global__ void sq_kernel(const float* __restrict__ feats) {
    int gw = (blockIdx.x * blockDim.x + threadIdx.x) >> 5;
    int lane = threadIdx.x & 31;
    if (gw >= NN) return;
    const float4* rowp = (const float4*)(feats + (size_t)gw * DD);
    float4 a = rowp[lane];
    float4 b = rowp[lane + 32];
    float s = a.x*a.x + a.y*a.y + a.z*a.z + a.w*a.w
            + b.x*b.x + b.y*b.y + b.z*b.z + b.w*b.w;
    #pragma unroll
    for (int o = 16; o; o >>= 1) s += __shfl_xor_sync(0xffffffffu, s, o);
    if (lane == 0) { g_sq[gw] = s; g_bcnt[gw] = 0; }
    __half2* dst = g_fh16 + (size_t)gw * (DD / 2);
    dst[lane * 2]          = __floats2half2_rn(a.x, a.y);
    dst[lane * 2 + 1]      = __floats2half2_rn(a.z, a.w);
    dst[64 + lane * 2]     = __floats2half2_rn(b.x, b.y);
    dst[64 + lane * 2 + 1] = __floats2half2_rn(b.z, b.w);
}

// ---------------- Kernel T: sample 512 cols -> per-row tau (20th-smallest key) ----------------
struct SmemT {
    __half A[BM][RSB];
    __half B[2][BN][RSB];
    float sqB[2][BN];
    float thr[BM];
    int   cnt[BM];
    unsigned long long best[BM][MST];
    unsigned long long cand[BM][BN];
};

__device__ __forceinline__ void prefetch_BT(SmemT& sm, int s, int j0, int tid) {
    #pragma unroll
    for (int t = 0; t < 8; ++t) {
        int idx = t * 256 + tid;
        int r = idx >> 5, ch = idx & 31;
        unsigned dst = smem_u32(&sm.B[s][r][ch * 8]);
        const void* src = (const char*)g_fh16 + (((size_t)(j0 + r) * DD) + ch * 8) * 2;
        CP16(dst, src);
    }
    if (tid < 16) {
        unsigned dst = smem_u32(&sm.sqB[s][tid * 4]);
        const void* src = g_sq + j0 + tid * 4;
        CP16(dst, src);
    }
}

__global__ void __launch_bounds__(256, 1) thresh_kernel() {
    extern __shared__ char raw[];
    SmemT& sm = *reinterpret_cast<SmemT*>(raw);
    const int tid = threadIdx.x;
    const int lane = tid & 31;
    const int w = tid >> 5;
    const int wr = w >> 1;
    const int wc = w & 1;
    const int i0 = blockIdx.x * BM;

    #pragma unroll
    for (int t = 0; t < 8; ++t) {
        int idx = t * 256 + tid;
        int r = idx >> 5, ch = idx & 31;
        unsigned dst = smem_u32(&sm.A[r][ch * 8]);
        const void* src = (const char*)g_fh16 + (((size_t)(i0 + r) * DD) + ch * 8) * 2;
        CP16(dst, src);
    }
    CP_COMMIT();
    prefetch_BT(sm, 0, 0, tid);
    CP_COMMIT();

    if (tid < BM) {
        sm.thr[tid] = __int_as_float(0x7f800000);
        sm.cnt[tid] = 0;
        #pragma unroll
        for (int t = 0; t < MST; ++t) sm.best[tid][t] = 0xFF800000FFFFFFFFull;
    }

    const unsigned aAddr = smem_u32(&sm.A[wr * 16 + (lane & 15)][0]) + ((lane >> 4) << 4);
    const int rowB = wc * 32 + ((lane >> 4) << 3) + (lane & 7);
    const unsigned bColOff = ((lane >> 3) & 1) << 4;
    unsigned bAddrBase[2];
    bAddrBase[0] = smem_u32(&sm.B[0][rowB][0]) + bColOff;
    bAddrBase[1] = smem_u32(&sm.B[1][rowB][0]) + bColOff;

    const int R0 = wr * 16 + (lane >> 2);
    const int R1 = R0 + 8;
    const int cBase = wc * 32 + 2 * (lane & 3);

    for (int jt = 0; jt < JTS; ++jt) {
        const int s = jt & 1;
        const int j0 = jt * BN;

        if (jt + 1 < JTS) {
            prefetch_BT(sm, s ^ 1, (jt + 1) * BN, tid);
            CP_COMMIT();
            CP_WAIT(1);
        } else {
            CP_WAIT(0);
        }
        __syncthreads();

        unsigned acc[4][2];
        #pragma unroll
        for (int nt = 0; nt < 4; ++nt) { acc[nt][0] = 0u; acc[nt][1] = 0u; }

        const unsigned bA = bAddrBase[s];
        #pragma unroll
        for (int ks = 0; ks < 16; ++ks) {
            unsigned a0, a1, a2, a3;
            LDSM_X4(a0, a1, a2, a3, aAddr + ks * 32);
            unsigned p00, p01, p10, p11, q00, q01, q10, q11;
            LDSM_X4(p00, p01, p10, p11, bA + ks * 32);
            LDSM_X4(q00, q01, q10, q11, bA + 16 * (RSB * 2) + ks * 32);
            MMA_F16(acc[0][0], acc[0][1], a0, a1, a2, a3, p00, p01);
            MMA_F16(acc[1][0], acc[1][1], a0, a1, a2, a3, p10, p11);
            MMA_F16(acc[2][0], acc[2][1], a0, a1, a2, a3, q00, q01);
            MMA_F16(acc[3][0], acc[3][1], a0, a1, a2, a3, q10, q11);
        }

        const float t0 = sm.thr[R0];
        const float t1 = sm.thr[R1];
        const float* sq = sm.sqB[s];
        #pragma unroll
        for (int nt = 0; nt < 4; ++nt) {
            const int c = cBase + nt * 8;
            float2 f0 = __half22float2(*(__half2*)&acc[nt][0]);
            float2 f1 = __half22float2(*(__half2*)&acc[nt][1]);
            float v00 = fmaf(-2.f, f0.x, sq[c]);
            float v01 = fmaf(-2.f, f0.y, sq[c + 1]);
            float v10 = fmaf(-2.f, f1.x, sq[c]);
            float v11 = fmaf(-2.f, f1.y, sq[c + 1]);
            if (v00 < t0) { int p = atomicAdd(&sm.cnt[R0], 1);
                sm.cand[R0][p] = ((unsigned long long)mono(v00) << 32) | (unsigned)(j0 + c); }
            if (v01 < t0) { int p = atomicAdd(&sm.cnt[R0], 1);
                sm.cand[R0][p] = ((unsigned long long)mono(v01) << 32) | (unsigned)(j0 + c + 1); }
            if (v10 < t1) { int p = atomicAdd(&sm.cnt[R1], 1);
                sm.cand[R1][p] = ((unsigned long long)mono(v10) << 32) | (unsigned)(j0 + c); }
            if (v11 < t1) { int p = atomicAdd(&sm.cnt[R1], 1);
                sm.cand[R1][p] = ((unsigned long long)mono(v11) << 32) | (unsigned)(j0 + c + 1); }
        }
        __syncthreads();

        if (tid < BM) {
            int n = sm.cnt[tid];
            if (n) {
                sm.cnt[tid] = 0;
                unsigned long long* bl = sm.best[tid];
                for (int q = 0; q < n; ++q) {
                    unsigned long long key = sm.cand[tid][q];
                    if (key < bl[MST - 1]) {
                        int p = MST - 1;
                        while (p > 0 && bl[p - 1] > key) { bl[p] = bl[p - 1]; --p; }
                        bl[p] = key;
                    }
                }
                sm.thr[tid] = unmono((unsigned)(bl[MST - 1] >> 32));
            }
        }
    }

    if (tid < BM)
        g_tau[i0 + tid] = unmono((unsigned)(sm.best[tid][MST - 1] >> 32));
}

// ---------------- Kernel S: cyclic symmetric screen, 512 threads (4 warps/SMSP) ----------------
struct SmemS {
    __half A[BM][RSB];
    __half B[2][BN][RSB];
    float sqB[2][BN], tauB[2][BN];
    float sqA[BM];
    float thr[BM];
    int   cnt[BM];
    unsigned long long best[BM][MS];
    unsigned long long cand[BM][BN];
    unsigned long long tval[TCAP];
    unsigned char tcol[TCAP];
    int tcnt;
};

__device__ __forceinline__ void prefetch_BS(SmemS& sm, int s, int j0, int tid) {
    #pragma unroll
    for (int t = 0; t < 4; ++t) {
        int idx = t * STH + tid;
        int r = idx >> 5, ch = idx & 31;
        unsigned dst = smem_u32(&sm.B[s][r][ch * 8]);
        const void* src = (const char*)g_fh16 + (((size_t)(j0 + r) * DD) + ch * 8) * 2;
        CP16(dst, src);
    }
    if (tid < 16) {
        unsigned dst = smem_u32(&sm.sqB[s][tid * 4]);
        CP16(dst, (const void*)(g_sq + j0 + tid * 4));
    } else if (tid < 32) {
        int t = tid - 16;
        unsigned dst = smem_u32(&sm.tauB[s][t * 4]);
        CP16(dst, (const void*)(g_tau + j0 + t * 4));
    }
}

__global__ void __launch_bounds__(STH, 1) screen_kernel() {
    extern __shared__ char raw[];
    SmemS& sm = *reinterpret_cast<SmemS*>(raw);
    const int tid = threadIdx.x;
    const int lane = tid & 31;
    const int w = tid >> 5;            // 0..15
    const int wr = w >> 2;             // 0..3 -> 16-row strip
    const int wc = w & 3;              // 0..3 -> 16-col strip
    const int it = blockIdx.x;
    const int i0 = it * BM;
    const int NT = (it < 64) ? 65 : 64;

    #pragma unroll
    for (int t = 0; t < 4; ++t) {
        int idx = t * STH + tid;
        int r = idx >> 5, ch = idx & 31;
        unsigned dst = smem_u32(&sm.A[r][ch * 8]);
        const void* src = (const char*)g_fh16 + (((size_t)(i0 + r) * DD) + ch * 8) * 2;
        CP16(dst, src);
    }
    CP_COMMIT();
    prefetch_BS(sm, 0, i0, tid);
    CP_COMMIT();

    if (tid < BM) {
        sm.sqA[tid] = g_sq[i0 + tid];
        sm.thr[tid] = __int_as_float(0x7f800000);
        sm.cnt[tid] = 0;
        #pragma unroll
        for (int t = 0; t < MS; ++t) sm.best[tid][t] = 0xFF800000FFFFFFFFull;
    }
    if (tid == 0) sm.tcnt = 0;

    // fragment addresses: warp tile 16 rows x 16 cols
    const unsigned aAddr = smem_u32(&sm.A[wr * 16 + (lane & 15)][0]) + ((lane >> 4) << 4);
    const int rowB = wc * 16 + ((lane >> 4) << 3) + (lane & 7);
    const unsigned bColOff = ((lane >> 3) & 1) << 4;
    unsigned bAddrBase[2];
    bAddrBase[0] = smem_u32(&sm.B[0][rowB][0]) + bColOff;
    bAddrBase[1] = smem_u32(&sm.B[1][rowB][0]) + bColOff;

    const int R0 = wr * 16 + (lane >> 2);
    const int R1 = R0 + 8;
    const int cBase = wc * 16 + 2 * (lane & 3);

    for (int t = 0; t < NT; ++t) {
        const int s = t & 1;
        const int jt = (it + t) & (NTILE - 1);
        const int j0 = jt * BN;
        const bool offdiag = (t != 0);

        if (t + 1 < NT) {
            prefetch_BS(sm, s ^ 1, ((it + t + 1) & (NTILE - 1)) * BN, tid);
            CP_COMMIT();
            CP_WAIT(1);
        } else {
            CP_WAIT(0);
        }
        __syncthreads();   // B[s]+sq/tau visible; prev flush + tcnt reset visible

        unsigned acc[2][2];
        acc[0][0] = 0u; acc[0][1] = 0u; acc[1][0] = 0u; acc[1][1] = 0u;

        const unsigned bA = bAddrBase[s];
        #pragma unroll
        for (int ks = 0; ks < 16; ++ks) {
            unsigned a0, a1, a2, a3;
            LDSM_X4(a0, a1, a2, a3, aAddr + ks * 32);
            unsigned p0, p1, p2, p3;
            LDSM_X4(p0, p1, p2, p3, bA + ks * 32);
            MMA_F16(acc[0][0], acc[0][1], a0, a1, a2, a3, p0, p1);
            MMA_F16(acc[1][0], acc[1][1], a0, a1, a2, a3, p2, p3);
        }

        const float t0 = sm.thr[R0];
        const float t1 = sm.thr[R1];
        const float sqa0 = sm.sqA[R0];
        const float sqa1 = sm.sqA[R1];
        const float* sq = sm.sqB[s];
        const float* tb = sm.tauB[s];
        #pragma unroll
        for (int nt = 0; nt < 2; ++nt) {
            const int c = cBase + nt * 8;
            float2 f0 = __half22float2(*(__half2*)&acc[nt][0]);   // row R0: c, c+1
            float2 f1 = __half22float2(*(__half2*)&acc[nt][1]);   // row R1: c, c+1
            float v00 = fmaf(-2.f, f0.x, sq[c]);
            float v01 = fmaf(-2.f, f0.y, sq[c + 1]);
            float v10 = fmaf(-2.f, f1.x, sq[c]);
            float v11 = fmaf(-2.f, f1.y, sq[c + 1]);
            if (v00 < t0) { int p = atomicAdd(&sm.cnt[R0], 1);
                sm.cand[R0][p] = ((unsigned long long)mono(v00) << 32) | (unsigned)(j0 + c); }
            if (v01 < t0) { int p = atomicAdd(&sm.cnt[R0], 1);
                sm.cand[R0][p] = ((unsigned long long)mono(v01) << 32) | (unsigned)(j0 + c + 1); }
            if (v10 < t1) { int p = atomicAdd(&sm.cnt[R1], 1);
                sm.cand[R1][p] = ((unsigned long long)mono(v10) << 32) | (unsigned)(j0 + c); }
            if (v11 < t1) { int p = atomicAdd(&sm.cnt[R1], 1);
                sm.cand[R1][p] = ((unsigned long long)mono(v11) << 32) | (unsigned)(j0 + c + 1); }
            if (offdiag) {
                float w00 = fmaf(-2.f, f0.x, sqa0);
                float w01 = fmaf(-2.f, f0.y, sqa0);
                float w10 = fmaf(-2.f, f1.x, sqa1);
                float w11 = fmaf(-2.f, f1.y, sqa1);
                if (w00 <= tb[c]) {
                    int p = atomicAdd(&sm.tcnt, 1);
                    if (p < TCAP) { sm.tval[p] = ((unsigned long long)mono(w00) << 32) | (unsigned)(i0 + R0); sm.tcol[p] = (unsigned char)c; }
                    else { int g = atomicAdd(&g_bcnt[j0 + c], 1); if (g < CAP) g_buf[(size_t)(j0 + c) * CAP + g] = ((unsigned long long)mono(w00) << 32) | (unsigned)(i0 + R0); }
                }
                if (w01 <= tb[c + 1]) {
                    int p = atomicAdd(&sm.tcnt, 1);
                    if (p < TCAP) { sm.tval[p] = ((unsigned long long)mono(w01) << 32) | (unsigned)(i0 + R0); sm.tcol[p] = (unsigned char)(c + 1); }
                    else { int g = atomicAdd(&g_bcnt[j0 + c + 1], 1); if (g < CAP) g_buf[(size_t)(j0 + c + 1) * CAP + g] = ((unsigned long long)mono(w01) << 32) | (unsigned)(i0 + R0); }
                }
                if (w10 <= tb[c]) {
                    int p = atomicAdd(&sm.tcnt, 1);
                    if (p < TCAP) { sm.tval[p] = ((unsigned long long)mono(w10) << 32) | (unsigned)(i0 + R1); sm.tcol[p] = (unsigned char)c; }
                    else { int g = atomicAdd(&g_bcnt[j0 + c], 1); if (g < CAP) g_buf[(size_t)(j0 + c) * CAP + g] = ((unsigned long long)mono(w10) << 32) | (unsigned)(i0 + R1); }
                }
                if (w11 <= tb[c + 1]) {
                    int p = atomicAdd(&sm.tcnt, 1);
                    if (p < TCAP) { sm.tval[p] = ((unsigned long long)mono(w11) << 32) | (unsigned)(i0 + R1); sm.tcol[p] = (unsigned char)(c + 1); }
                    else { int g = atomicAdd(&g_bcnt[j0 + c + 1], 1); if (g < CAP) g_buf[(size_t)(j0 + c + 1) * CAP + g] = ((unsigned long long)mono(w11) << 32) | (unsigned)(i0 + R1); }
                }
            }
        }
        __syncthreads();   // epilogue complete: tcnt/tval/tcol and cand/cnt stable

        // cooperative drain of staged transpose appends
        {
            int n = sm.tcnt;
            if (n > TCAP) n = TCAP;
            for (int q = tid; q < n; q += STH) {
                int trow = j0 + (int)sm.tcol[q];
                int p = atomicAdd(&g_bcnt[trow], 1);
                if (p < CAP) g_buf[(size_t)trow * CAP + p] = sm.tval[q];
            }
        }
        // local flush (tid<BM) concurrent with the drain
        if (tid < BM) {
            int n = sm.cnt[tid];
            if (n) {
                sm.cnt[tid] = 0;
                unsigned long long* bl = sm.best[tid];
                for (int q = 0; q < n; ++q) {
                    unsigned long long key = sm.cand[tid][q];
                    if (key < bl[MS - 1]) {
                        int p = MS - 1;
                        while (p > 0 && bl[p - 1] > key) { bl[p] = bl[p - 1]; --p; }
                        bl[p] = key;
                    }
                }
                sm.thr[tid] = unmono((unsigned)(bl[MS - 1] >> 32));
            }
        }
        __syncthreads();   // drain + flush complete
        if (tid == 0) sm.tcnt = 0;
    }
    __syncthreads();

    for (int idx = tid; idx < BM * MS; idx += STH) {
        int r = idx / MS, t = idx % MS;
        g_loc[(size_t)(i0 + r) * MS + t] = sm.best[r][t];
    }
}

// ---------------- Kernel L: warp-per-row merge of local top-24 + buffer -> top-28 ----------------
__global__ void __launch_bounds__(256) sel_kernel() {
    __shared__ unsigned long long ch[8][32][13];
    const int lane = threadIdx.x & 31;
    const int w = threadIdx.x >> 5;
    const int row = blockIdx.x * 8 + w;

    unsigned long long* my = ch[w][lane];
    int len = 0;
    if (lane < MS) { my[0] = g_loc[(size_t)row * MS + lane]; len = 1; }
    int cnt = g_bcnt[row];
    if (cnt > SCAP) cnt = SCAP;
    const unsigned long long* bp = g_buf + (size_t)row * CAP;
    for (int q = lane; q < cnt; q += 32) {
        unsigned long long key = bp[q];
        int p = len++;
        while (p > 0 && my[p - 1] > key) { my[p] = my[p - 1]; --p; }
        my[p] = key;
    }
    __syncwarp();

    int ptr = 0;
    for (int sel = 0; sel < RS28; ++sel) {
        unsigned long long h = (ptr < len) ? my[ptr] : ULLINF;
        unsigned long long M = h;
        #pragma unroll
        for (int o = 16; o; o >>= 1) {
            unsigned long long v = __shfl_xor_sync(0xffffffffu, M, o);
            M = (v < M) ? v : M;
        }
        unsigned b = __ballot_sync(0xffffffffu, h == M);
        if (lane == (__ffs(b) - 1)) ++ptr;
        if (lane == 0) g_cand[(size_t)row * RS28 + sel] = M;
    }
}

// ---------------- Kernel R: exact fp32 refine of 28 survivors -> exact top-17 ----------------
__global__ void refine_kernel(const float* __restrict__ feats) {
    int row = (blockIdx.x * blockDim.x + threadIdx.x) >> 5;
    int lane = threadIdx.x & 31;
    if (row >= NN) return;

    const float* base = feats + (size_t)row * DD;
    float4 a0 = *(const float4*)(base + lane * 4);
    float4 a1 = *(const float4*)(base + 128 + lane * 4);
    float own[8] = {a0.x, a0.y, a0.z, a0.w, a1.x, a1.y, a1.z, a1.w};

    unsigned long long mykey = ULLINF;

    #pragma unroll 4
    for (int t = 0; t < RS28; ++t) {
        unsigned long long ak = g_cand[(size_t)row * RS28 + t];
        int j = (ak == ULLINF) ? 0 : (int)(unsigned)(ak & 0xffffffffull);
        const float* nb = feats + (size_t)j * DD;
        float4 b0 = *(const float4*)(nb + lane * 4);
        float4 b1 = *(const float4*)(nb + 128 + lane * 4);
        float p = own[0]*b0.x + own[1]*b0.y + own[2]*b0.z + own[3]*b0.w
                + own[4]*b1.x + own[5]*b1.y + own[6]*b1.z + own[7]*b1.w;
        #pragma unroll
        for (int o = 16; o; o >>= 1) p += __shfl_xor_sync(0xffffffffu, p, o);
        float val = fmaf(-2.f, p, g_sq[j]);
        unsigned long long key = (ak == ULLINF) ? ULLINF
                               : (((unsigned long long)mono(val) << 32) | (unsigned)j);
        if (lane == t) mykey = key;
    }

    int rank = 0;
    #pragma unroll
    for (int s = 0; s < RS28; ++s) {
        unsigned long long ok = __shfl_sync(0xffffffffu, mykey, s);
        rank += (ok < mykey);
    }
    if (lane < RS28 && rank < KSEL && mykey != ULLINF)
        g_best[(size_t)row * KSEL + rank] = mykey;
}

// ---------------- Kernel C: mutual mask + sparse softmax + AV + residual + normalize ----------------
__global__ void fuse_kernel(const float* __restrict__ feats, float* __restrict__ out) {
    int gw = (blockIdx.x * blockDim.x + threadIdx.x) >> 5;
    int lane = threadIdx.x & 31;
    if (gw >= NN) return;
    const int row = gw;
    const float* base = feats + (size_t)row * DD;
    float4 a0 = *(const float4*)(base + lane * 4);
    float4 a1 = *(const float4*)(base + 128 + lane * 4);
    float own[8] = {a0.x, a0.y, a0.z, a0.w, a1.x, a1.y, a1.z, a1.w};

    int my_nbr = -1;
    int cnt = 0;
    #pragma unroll
    for (int t = 0; t < KSEL; ++t) {
        unsigned long long key = g_best[(size_t)row * KSEL + t];
        int j = (int)(unsigned)(key & 0xffffffffull);
        if (j != row && cnt < KK) {
            if (cnt == lane) my_nbr = j;
            cnt++;
        }
    }

    bool found = false;
    if (lane < KK && my_nbr >= 0) {
        #pragma unroll
        for (int t = 0; t < KSEL; ++t) {
            unsigned long long key = g_best[(size_t)my_nbr * KSEL + t];
            if ((int)(unsigned)(key & 0xffffffffull) == row) found = true;
        }
    }
    unsigned mmask = __ballot_sync(0xffffffffu, found) & 0xffffu;

    float m = 1.0f, Z = 1.0f;
    float acc[8];
    #pragma unroll
    for (int e = 0; e < 8; ++e) acc[e] = own[e];

    for (int l = 0; l < KK; ++l) {
        if (!((mmask >> l) & 1u)) continue;
        int j = __shfl_sync(0xffffffffu, my_nbr, l);
        const float* nb = feats + (size_t)j * DD;
        float4 b0 = *(const float4*)(nb + lane * 4);
        float4 b1 = *(const float4*)(nb + 128 + lane * 4);
        float v[8] = {b0.x, b0.y, b0.z, b0.w, b1.x, b1.y, b1.z, b1.w};
        float p = 0.f;
        #pragma unroll
        for (int e = 0; e < 8; ++e) p = fmaf(own[e], v[e], p);
        #pragma unroll
        for (int o = 16; o; o >>= 1) p += __shfl_xor_sync(0xffffffffu, p, o);
        if (p > m) {
            float f = expf(m - p);
            Z = Z * f + 1.0f;
            #pragma unroll
            for (int e = 0; e < 8; ++e) acc[e] = fmaf(acc[e], f, v[e]);
            m = p;
        } else {
            float wgt = expf(p - m);
            Z += wgt;
            #pragma unroll
            for (int e = 0; e < 8; ++e) acc[e] = fmaf(wgt, v[e], acc[e]);
        }
    }

    float invZ = 1.0f / Z;
    float fcm[8];
    float ss = 0.f;
    #pragma unroll
    for (int e = 0; e < 8; ++e) {
        fcm[e] = fmaf(acc[e], invZ, own[e]);
        ss = fmaf(fcm[e], fcm[e], ss);
    }
    #pragma unroll
    for (int o = 16; o; o >>= 1) ss += __shfl_xor_sync(0xffffffffu, ss, o);
    float inv = 1.0f / fmaxf(sqrtf(ss), 1e-12f);

    float* op = out + (size_t)row * DD;
    *(float4*)(op + lane * 4)       = make_float4(fcm[0]*inv, fcm[1]*inv, fcm[2]*inv, fcm[3]*inv);
    *(float4*)(op + 128 + lane * 4) = make_float4(fcm[4]*inv, fcm[5]*inv, fcm[6]*inv, fcm[7]*inv);
}

// ---------------- launch ----------------
extern "C" void kernel_launch(void* const* d_in, const int* in_sizes, int n_in,
                              void* d_out, int out_size) {
    const float* feats = (const float*)d_in[0];
    float* out = (float*)d_out;
    (void)in_sizes; (void)n_in; (void)out_size;

    cudaFuncSetAttribute(thresh_kernel, cudaFuncAttributeMaxDynamicSharedMemorySize,
                         (int)sizeof(SmemT));
    cudaFuncSetAttribute(screen_kernel, cudaFuncAttributeMaxDynamicSharedMemorySize,
                         (int)sizeof(SmemS));

    sq_kernel<<<NN / 8, 256>>>(feats);
    thresh_kernel<<<NN / BM, 256, sizeof(SmemT)>>>();
    screen_kernel<<<NTILE, STH, sizeof(SmemS)>>>();
    sel_kernel<<<NN / 8, 256>>>();
    refine_kernel<<<NN / 8, 256>>>(feats);
    fuse_kernel<<<NN / 8, 256>>>(feats, out);
}